// round 10
// baseline (speedup 1.0000x reference)
#include <cuda_runtime.h>

#define C 38
#define PAD_IDX 0
#define O_IDX 1
#define TILE 128
#define ROWS 129
#define TDIM 160          // 5 warps
#define NWARPS 5
#define F2 19             // 38 floats = 19 float2
#define NPAIR 18          // C/2 - 1 canonical invalid columns
#define LOG2E 1.44269504088896f

// ---------------- device-global scratch (no allocations allowed) ----------------
__device__ int g_ncols;
__device__ int g_col[C], g_k[C], g_off[C];
__device__ float g_base[C], g_sign[C];
__device__ unsigned char g_idx[C * C];
__device__ int g_spec2;         // canonical BIO structure -> fused fast path
__device__ float g_ubase, g_usign;
__device__ float g_partials[8 * 4096];
__device__ unsigned int g_ticket;

__device__ __forceinline__ void cp_async8(unsigned int dst, const void* src) {
    asm volatile("cp.async.ca.shared.global [%0], [%1], 8;" :: "r"(dst), "l"(src));
}

// ---------------- kernel A: build compact transition descriptor ----------------
__global__ void build_desc_kernel(const float* __restrict__ mask) {
    __shared__ float s_mask[C * C];
    __shared__ int s_n[C];
    __shared__ int s_slot[C], s_woff[C];
    const int tid = threadIdx.x;

    for (int i = tid; i < C * C; i += blockDim.x) s_mask[i] = mask[i];
    __syncthreads();

    if (tid < C) {
        int n = 0;
        for (int p = 0; p < C; p++)
            if (s_mask[p * C + tid] < 0.5f) n++;
        s_n[tid] = n;
    }
    __syncthreads();

    if (tid == 0) {
        int ncols = 0, off = 0;
        for (int c = 0; c < C; c++) {
            int n = s_n[c];
            if (n == 0) { s_slot[c] = -1; continue; }
            s_slot[c] = ncols;
            s_woff[c] = off;
            g_col[ncols] = c;
            g_off[ncols] = off;
            if (2 * n <= C) {
                g_base[ncols] = 0.f; g_sign[ncols] = 1.f; g_k[ncols] = n; off += n;
            } else {
                g_base[ncols] = 1.f; g_sign[ncols] = -1.f; g_k[ncols] = C - n; off += C - n;
            }
            ncols++;
        }
        g_ncols = ncols;
        g_ticket = 0u;
    }
    __syncthreads();

    if (tid < C && s_slot[tid] >= 0) {
        const int c = tid;
        const int n = s_n[c];
        int off = s_woff[c];
        if (2 * n <= C) {
            for (int p = 0; p < C; p++)
                if (s_mask[p * C + c] < 0.5f) g_idx[off++] = (unsigned char)p;
        } else {
            for (int p = 0; p < C; p++)
                if (s_mask[p * C + c] >= 0.5f) g_idx[off++] = (unsigned char)p;
        }
    }
    __syncthreads();

    // canonical detection: ncols == NPAIR, uniform k==2/base/sign, and slot m
    // (0-based) has complement pair {2(m+1), 2(m+1)+1} with column 2(m+1)+1.
    if (tid == 0) {
        const int nc = g_ncols;
        int spec = (nc == NPAIR) ? 1 : 0;
        for (int j = 0; j < nc && spec; j++) {
            const int off = g_off[j];
            if (g_k[j] != 2 || g_base[j] != g_base[0] || g_sign[j] != g_sign[0])
                spec = 0;
            else {
                const int i0 = g_idx[off], i1 = g_idx[off + 1];
                if (i0 != 2 * (j + 1) || i1 != i0 + 1 || g_col[j] != i0 + 1)
                    spec = 0;
            }
        }
        if (nc > 0) { g_ubase = g_base[0]; g_usign = g_sign[0]; }
        g_spec2 = spec;
    }
}

// ---------------- kernel B: main fused loss kernel ----------------
__global__ void __launch_bounds__(TDIM, 10) ner_main_kernel(
    const float* __restrict__ logits, const int* __restrict__ labels,
    float* __restrict__ out, int T, int nblocks) {
    __shared__ float2 sm2[ROWS * F2];            // logits tile -> (pairsum,eodd) image
    __shared__ float s_invs[ROWS];
    __shared__ unsigned char s_valid[ROWS];
    __shared__ float s_red[NWARPS * 8];
    __shared__ int s_islast;

    const int tid = threadIdx.x;
    const int chunks = T / TILE;
    const int b = blockIdx.x / chunks;
    const int chunk = blockIdx.x % chunks;
    const int start = chunk * TILE;
    const bool has_prev = (chunk > 0);
    const int spec2 = g_spec2;
    const float ubase = g_ubase, usign = g_usign;

    if (!has_prev && tid == 0) s_valid[0] = 0;

    // cp.async staging: shared tile is a packed image of global (stride == C)
    const int row0 = has_prev ? 0 : 1;
    {
        const int nrows = has_prev ? ROWS : TILE;
        const float2* g2 = (const float2*)(
            logits + ((long long)b * T + start - (has_prev ? 1 : 0)) * (long long)C);
        unsigned int sbase = (unsigned int)__cvta_generic_to_shared(sm2 + row0 * F2);
        const int total2 = nrows * F2;
        for (int i = tid; i < total2; i += TDIM)
            cp_async8(sbase + (unsigned int)i * 8u, g2 + i);
        asm volatile("cp.async.commit_group;");
    }

    // prefetch label while tile is in flight
    const bool row_active = (tid < ROWS) && (has_prev || tid >= 1);
    int label = PAD_IDX;
    if (row_active)
        label = labels[(long long)b * T + (start - 1 + tid)];

    asm volatile("cp.async.wait_group 0;");
    __syncthreads();

    float ce = 0.f, miss = 0.f, fp = 0.f, trans = 0.f;
    bool ce_f = false, miss_f = false, fp_f = false, trans_f = false;

    // -------- pass 1: softmax per row; write (pairsum, eodd) pairs in-place -----
    if (row_active) {
        const int r = tid;
        float2* row2 = sm2 + r * F2;
        s_valid[r] = (unsigned char)(label != PAD_IDX);
        const float gold_l = ((const float*)row2)[label];  // read before overwrite

        float2 v = row2[0];
        const float e0a = exp2f(v.x * LOG2E);
        const float eO = exp2f(v.y * LOG2E);               // O_IDX == 1
        float s0 = e0a + eO, s1 = 0.f;

        if (spec2) {
            #pragma unroll
            for (int k = 1; k < F2; k++) {
                v = row2[k];
                const float e0 = exp2f(v.x * LOG2E);
                const float e1 = exp2f(v.y * LOG2E);
                const float ps = e0 + e1;
                if (k & 1) s1 += ps; else s0 += ps;
                row2[k - 1] = make_float2(ps, e1);         // k-1 < k: no hazard
            }
        } else {
            #pragma unroll
            for (int k = 1; k < F2; k++) {
                v = row2[k];
                const float e0 = exp2f(v.x * LOG2E);
                const float e1 = exp2f(v.y * LOG2E);
                if (k & 1) s1 += e0 + e1; else s0 += e0 + e1;
                row2[k] = make_float2(e0, e1);             // keep full exps
            }
            row2[0] = make_float2(e0a, eO);
        }
        const float s = s0 + s1;
        const float invs = 1.f / s;
        s_invs[r] = invs;

        if (r >= 1 && label != PAD_IDX) {
            ce = (__logf(s) - gold_l); ce_f = true;
            const float p_o = eO * invs;
            if (label == O_IDX) { fp = -__logf(fmaxf(p_o, 1e-8f)); fp_f = true; }
            else { miss = -__logf(fmaxf(1.f - p_o, 1e-8f)); miss_f = true; }
        }
    }
    __syncthreads();

    // -------- pass 2: transition mass for pair (t, t+1), thread t owns it --------
    if (tid < TILE) {
        const int t = tid;
        if (s_valid[t] && s_valid[t + 1]) {
            const float2* tp = sm2 + t * F2;               // (pairsum, eodd) of row t
            const float2* cp = sm2 + (t + 1) * F2;
            float msum;
            if (spec2) {
                const float si = usign * s_invs[t];
                float m0 = 0.f, m1 = 0.f;
                #pragma unroll
                for (int k = 0; k < NPAIR; k += 2) {
                    const float2 a = tp[k];
                    const float2 bq = cp[k];
                    m0 = fmaf(bq.y, fmaf(si, a.x, ubase), m0);
                    const float2 a2 = tp[k + 1];
                    const float2 b2 = cp[k + 1];
                    m1 = fmaf(b2.y, fmaf(si, a2.x, ubase), m1);
                }
                msum = m0 + m1;
            } else {
                const float* pp = (const float*)tp;
                const float* pc = (const float*)cp;
                const float invp = s_invs[t];
                msum = 0.f;
                const int nc = g_ncols;
                for (int j = 0; j < nc; j++) {
                    const int off = g_off[j];
                    const int k = g_k[j];
                    float acc = 0.f;
                    for (int i = 0; i < k; i++) acc += pp[g_idx[off + i]];
                    const float term = fmaf(g_sign[j] * invp, acc, g_base[j]);
                    msum = fmaf(pc[g_col[j]], term, msum);
                }
            }
            trans = msum * s_invs[t + 1];
            trans_f = true;
        }
    }

    // -------- block reduction: 4 float sums + 4 popc counts --------
    const unsigned full = 0xffffffffu;
    const unsigned b_ce = __ballot_sync(full, ce_f);
    const unsigned b_ms = __ballot_sync(full, miss_f);
    const unsigned b_fp = __ballot_sync(full, fp_f);
    const unsigned b_tr = __ballot_sync(full, trans_f);
    float sums[4] = {ce, miss, fp, trans};
    #pragma unroll
    for (int k = 0; k < 4; k++) {
        float x = sums[k];
        #pragma unroll
        for (int o = 16; o > 0; o >>= 1) x += __shfl_down_sync(full, x, o);
        sums[k] = x;
    }
    const int warp = tid >> 5, lane = tid & 31;
    if (lane == 0) {
        s_red[warp * 8 + 0] = sums[0];
        s_red[warp * 8 + 1] = (float)__popc(b_ce);
        s_red[warp * 8 + 2] = sums[1];
        s_red[warp * 8 + 3] = (float)__popc(b_ms);
        s_red[warp * 8 + 4] = sums[2];
        s_red[warp * 8 + 5] = (float)__popc(b_fp);
        s_red[warp * 8 + 6] = sums[3];
        s_red[warp * 8 + 7] = (float)__popc(b_tr);
    }
    __syncthreads();
    if (tid == 0) {
        #pragma unroll
        for (int k = 0; k < 8; k++) {
            float a = 0.f;
            #pragma unroll
            for (int w = 0; w < NWARPS; w++) a += s_red[w * 8 + k];
            g_partials[blockIdx.x * 8 + k] = a;
        }
        __threadfence();
        unsigned int t = atomicAdd(&g_ticket, 1u);
        s_islast = (t == (unsigned int)(nblocks - 1)) ? 1 : 0;
    }
    __syncthreads();

    // -------- last block: deterministic final reduction + output --------
    if (s_islast) {
        float acc[8] = {0.f, 0.f, 0.f, 0.f, 0.f, 0.f, 0.f, 0.f};
        for (int i = tid; i < nblocks; i += TDIM) {
            #pragma unroll
            for (int k = 0; k < 8; k++) acc[k] += g_partials[i * 8 + k];
        }
        #pragma unroll
        for (int k = 0; k < 8; k++) {
            float x = acc[k];
            #pragma unroll
            for (int o = 16; o > 0; o >>= 1) x += __shfl_down_sync(full, x, o);
            acc[k] = x;
        }
        if (lane == 0) {
            #pragma unroll
            for (int k = 0; k < 8; k++) s_red[warp * 8 + k] = acc[k];
        }
        __syncthreads();
        if (tid == 0) {
            float r[8];
            #pragma unroll
            for (int k = 0; k < 8; k++) {
                float a = 0.f;
                #pragma unroll
                for (int w = 0; w < NWARPS; w++) a += s_red[w * 8 + k];
                r[k] = a;
            }
            const float cem   = r[0] / fmaxf(r[1], 1.f);
            const float missm = r[2] / fmaxf(r[3], 1.f);
            const float fpm   = r[4] / fmaxf(r[5], 1.f);
            const float trm   = r[6] / fmaxf(r[7], 1.f);
            out[0] = cem + 1.2f * missm + 1.0f * fpm + 0.8f * trm;
        }
    }
}

// ---------------- launch ----------------
extern "C" void kernel_launch(void* const* d_in, const int* in_sizes, int n_in,
                              void* d_out, int out_size) {
    const float* logits = (const float*)d_in[0];
    const int* labels = (const int*)d_in[1];
    const float* mask = (const float*)d_in[2];

    const int BT = in_sizes[1];
    const int T = 4096;
    const int B = BT / T;
    const int chunks = T / TILE;
    const int nblocks = B * chunks;   // 4096

    build_desc_kernel<<<1, 256>>>(mask);
    ner_main_kernel<<<nblocks, TDIM>>>(logits, labels, (float*)d_out, T, nblocks);
}

// round 11
// speedup vs baseline: 1.7600x; 1.7600x over previous
#include <cuda_runtime.h>

#define C 38
#define PAD_IDX 0
#define O_IDX 1
#define TILE 256
#define ROWS 257
#define TDIM 288          // 9 warps: rows 0..256 thread-parallel
#define NWARPS 9
#define F2 19             // 38 floats = 19 float2
#define NPAIR 18          // canonical invalid columns
#define LOG2E 1.44269504088896f

// ---------------- device-global scratch (no allocations allowed) ----------------
__device__ int g_ncols;
__device__ int g_col[C], g_k[C], g_off[C];
__device__ float g_base[C], g_sign[C];
__device__ unsigned char g_idx[C * C];
__device__ int g_spec2;         // canonical BIO structure -> fused fast path
__device__ float g_ubase, g_usign;
__device__ float g_partials[8 * 2048];
__device__ unsigned int g_ticket;

__device__ __forceinline__ void cp_async8(unsigned int dst, const void* src) {
    asm volatile("cp.async.ca.shared.global [%0], [%1], 8;" :: "r"(dst), "l"(src));
}

// ---------------- kernel A: build compact transition descriptor ----------------
__global__ void build_desc_kernel(const float* __restrict__ mask) {
    __shared__ float s_mask[C * C];
    __shared__ int s_n[C];
    __shared__ int s_slot[C], s_woff[C];
    const int tid = threadIdx.x;

    for (int i = tid; i < C * C; i += blockDim.x) s_mask[i] = mask[i];
    __syncthreads();

    if (tid < C) {
        int n = 0;
        for (int p = 0; p < C; p++)
            if (s_mask[p * C + tid] < 0.5f) n++;
        s_n[tid] = n;
    }
    __syncthreads();

    if (tid == 0) {
        int ncols = 0, off = 0;
        for (int c = 0; c < C; c++) {
            int n = s_n[c];
            if (n == 0) { s_slot[c] = -1; continue; }
            s_slot[c] = ncols;
            s_woff[c] = off;
            g_col[ncols] = c;
            g_off[ncols] = off;
            if (2 * n <= C) {
                g_base[ncols] = 0.f; g_sign[ncols] = 1.f; g_k[ncols] = n; off += n;
            } else {
                g_base[ncols] = 1.f; g_sign[ncols] = -1.f; g_k[ncols] = C - n; off += C - n;
            }
            ncols++;
        }
        g_ncols = ncols;
        g_ticket = 0u;
    }
    __syncthreads();

    if (tid < C && s_slot[tid] >= 0) {
        const int c = tid;
        const int n = s_n[c];
        int off = s_woff[c];
        if (2 * n <= C) {
            for (int p = 0; p < C; p++)
                if (s_mask[p * C + c] < 0.5f) g_idx[off++] = (unsigned char)p;
        } else {
            for (int p = 0; p < C; p++)
                if (s_mask[p * C + c] >= 0.5f) g_idx[off++] = (unsigned char)p;
        }
    }
    __syncthreads();

    // canonical detection: ncols == NPAIR, uniform k==2/base/sign, and slot m
    // (0-based) has complement pair {2(m+1), 2(m+1)+1} with column 2(m+1)+1.
    if (tid == 0) {
        const int nc = g_ncols;
        int spec = (nc == NPAIR) ? 1 : 0;
        for (int j = 0; j < nc && spec; j++) {
            const int off = g_off[j];
            if (g_k[j] != 2 || g_base[j] != g_base[0] || g_sign[j] != g_sign[0])
                spec = 0;
            else {
                const int i0 = g_idx[off], i1 = g_idx[off + 1];
                if (i0 != 2 * (j + 1) || i1 != i0 + 1 || g_col[j] != i0 + 1)
                    spec = 0;
            }
        }
        if (nc > 0) { g_ubase = g_base[0]; g_usign = g_sign[0]; }
        g_spec2 = spec;
    }
}

// ---------------- kernel B: main fused loss kernel ----------------
__global__ void __launch_bounds__(TDIM, 5) ner_main_kernel(
    const float* __restrict__ logits, const int* __restrict__ labels,
    float* __restrict__ out, int T, int nblocks) {
    __shared__ float2 sm2[ROWS * F2];            // logits tile -> (pairsum,eodd) image
    __shared__ float s_invs[ROWS];
    __shared__ unsigned char s_valid[ROWS];
    __shared__ float s_red[NWARPS * 8];
    __shared__ int s_islast;

    const int tid = threadIdx.x;
    const int chunks = T / TILE;
    const int b = blockIdx.x / chunks;
    const int chunk = blockIdx.x % chunks;
    const int start = chunk * TILE;
    const bool has_prev = (chunk > 0);
    const int spec2 = g_spec2;
    const float ubase = g_ubase, usign = g_usign;

    if (!has_prev && tid == 0) s_valid[0] = 0;

    // cp.async staging: shared tile is a packed image of global (stride == C)
    const int row0 = has_prev ? 0 : 1;
    {
        const int nrows = has_prev ? ROWS : TILE;
        const float2* g2 = (const float2*)(
            logits + ((long long)b * T + start - (has_prev ? 1 : 0)) * (long long)C);
        unsigned int sbase = (unsigned int)__cvta_generic_to_shared(sm2 + row0 * F2);
        const int total2 = nrows * F2;
        for (int i = tid; i < total2; i += TDIM)
            cp_async8(sbase + (unsigned int)i * 8u, g2 + i);
        asm volatile("cp.async.commit_group;");
    }

    // prefetch label while tile is in flight
    const bool row_active = (tid < ROWS) && (has_prev || tid >= 1);
    int label = PAD_IDX;
    if (row_active)
        label = labels[(long long)b * T + (start - 1 + tid)];

    asm volatile("cp.async.wait_group 0;");
    __syncthreads();

    float ce = 0.f, miss = 0.f, fp = 0.f, trans = 0.f;
    bool ce_f = false, miss_f = false, fp_f = false, trans_f = false;

    // -------- pass 1: softmax per row; write (pairsum, eodd) pairs in-place -----
    if (row_active) {
        const int r = tid;
        float2* row2 = sm2 + r * F2;
        s_valid[r] = (unsigned char)(label != PAD_IDX);
        const float gold_l = ((const float*)row2)[label];  // read before overwrite

        float2 v = row2[0];
        const float e0a = exp2f(v.x * LOG2E);
        const float eO = exp2f(v.y * LOG2E);               // O_IDX == 1
        float s0 = e0a + eO, s1 = 0.f;

        if (spec2) {
            #pragma unroll
            for (int k = 1; k < F2; k++) {
                v = row2[k];
                const float e0 = exp2f(v.x * LOG2E);
                const float e1 = exp2f(v.y * LOG2E);
                const float ps = e0 + e1;
                if (k & 1) s1 += ps; else s0 += ps;
                row2[k - 1] = make_float2(ps, e1);         // k-1 < k: no hazard
            }
        } else {
            #pragma unroll
            for (int k = 1; k < F2; k++) {
                v = row2[k];
                const float e0 = exp2f(v.x * LOG2E);
                const float e1 = exp2f(v.y * LOG2E);
                if (k & 1) s1 += e0 + e1; else s0 += e0 + e1;
                row2[k] = make_float2(e0, e1);             // keep full exps
            }
            row2[0] = make_float2(e0a, eO);
        }
        const float s = s0 + s1;
        const float invs = 1.f / s;
        s_invs[r] = invs;

        if (r >= 1 && label != PAD_IDX) {
            ce = (__logf(s) - gold_l); ce_f = true;
            const float p_o = eO * invs;
            if (label == O_IDX) { fp = -__logf(fmaxf(p_o, 1e-8f)); fp_f = true; }
            else { miss = -__logf(fmaxf(1.f - p_o, 1e-8f)); miss_f = true; }
        }
    }
    __syncthreads();

    // -------- pass 2: transition mass for pair (t, t+1), thread t owns it --------
    if (tid < TILE) {
        const int t = tid;
        if (s_valid[t] && s_valid[t + 1]) {
            const float2* tp = sm2 + t * F2;               // (pairsum, eodd) of row t
            const float2* cp = sm2 + (t + 1) * F2;
            float msum;
            if (spec2) {
                const float si = usign * s_invs[t];
                float m0 = 0.f, m1 = 0.f;
                #pragma unroll
                for (int k = 0; k < NPAIR; k += 2) {
                    const float2 a = tp[k];
                    const float2 bq = cp[k];
                    m0 = fmaf(bq.y, fmaf(si, a.x, ubase), m0);
                    const float2 a2 = tp[k + 1];
                    const float2 b2 = cp[k + 1];
                    m1 = fmaf(b2.y, fmaf(si, a2.x, ubase), m1);
                }
                msum = m0 + m1;
            } else {
                const float* pp = (const float*)tp;
                const float* pc = (const float*)cp;
                const float invp = s_invs[t];
                msum = 0.f;
                const int nc = g_ncols;
                for (int j = 0; j < nc; j++) {
                    const int off = g_off[j];
                    const int k = g_k[j];
                    float acc = 0.f;
                    for (int i = 0; i < k; i++) acc += pp[g_idx[off + i]];
                    const float term = fmaf(g_sign[j] * invp, acc, g_base[j]);
                    msum = fmaf(pc[g_col[j]], term, msum);
                }
            }
            trans = msum * s_invs[t + 1];
            trans_f = true;
        }
    }

    // -------- block reduction: 4 float sums + 4 popc counts --------
    const unsigned full = 0xffffffffu;
    const unsigned b_ce = __ballot_sync(full, ce_f);
    const unsigned b_ms = __ballot_sync(full, miss_f);
    const unsigned b_fp = __ballot_sync(full, fp_f);
    const unsigned b_tr = __ballot_sync(full, trans_f);
    float sums[4] = {ce, miss, fp, trans};
    #pragma unroll
    for (int k = 0; k < 4; k++) {
        float x = sums[k];
        #pragma unroll
        for (int o = 16; o > 0; o >>= 1) x += __shfl_down_sync(full, x, o);
        sums[k] = x;
    }
    const int warp = tid >> 5, lane = tid & 31;
    if (lane == 0) {
        s_red[warp * 8 + 0] = sums[0];
        s_red[warp * 8 + 1] = (float)__popc(b_ce);
        s_red[warp * 8 + 2] = sums[1];
        s_red[warp * 8 + 3] = (float)__popc(b_ms);
        s_red[warp * 8 + 4] = sums[2];
        s_red[warp * 8 + 5] = (float)__popc(b_fp);
        s_red[warp * 8 + 6] = sums[3];
        s_red[warp * 8 + 7] = (float)__popc(b_tr);
    }
    __syncthreads();
    if (tid == 0) {
        #pragma unroll
        for (int k = 0; k < 8; k++) {
            float a = 0.f;
            #pragma unroll
            for (int w = 0; w < NWARPS; w++) a += s_red[w * 8 + k];
            g_partials[blockIdx.x * 8 + k] = a;
        }
        __threadfence();
        unsigned int t = atomicAdd(&g_ticket, 1u);
        s_islast = (t == (unsigned int)(nblocks - 1)) ? 1 : 0;
    }
    __syncthreads();

    // -------- last block: deterministic final reduction + output --------
    if (s_islast) {
        float acc[8] = {0.f, 0.f, 0.f, 0.f, 0.f, 0.f, 0.f, 0.f};
        for (int i = tid; i < nblocks; i += TDIM) {
            #pragma unroll
            for (int k = 0; k < 8; k++) acc[k] += g_partials[i * 8 + k];
        }
        #pragma unroll
        for (int k = 0; k < 8; k++) {
            float x = acc[k];
            #pragma unroll
            for (int o = 16; o > 0; o >>= 1) x += __shfl_down_sync(full, x, o);
            acc[k] = x;
        }
        if (lane == 0) {
            #pragma unroll
            for (int k = 0; k < 8; k++) s_red[warp * 8 + k] = acc[k];
        }
        __syncthreads();
        if (tid == 0) {
            float r[8];
            #pragma unroll
            for (int k = 0; k < 8; k++) {
                float a = 0.f;
                #pragma unroll
                for (int w = 0; w < NWARPS; w++) a += s_red[w * 8 + k];
                r[k] = a;
            }
            const float cem   = r[0] / fmaxf(r[1], 1.f);
            const float missm = r[2] / fmaxf(r[3], 1.f);
            const float fpm   = r[4] / fmaxf(r[5], 1.f);
            const float trm   = r[6] / fmaxf(r[7], 1.f);
            out[0] = cem + 1.2f * missm + 1.0f * fpm + 0.8f * trm;
        }
    }
}

// ---------------- launch ----------------
extern "C" void kernel_launch(void* const* d_in, const int* in_sizes, int n_in,
                              void* d_out, int out_size) {
    const float* logits = (const float*)d_in[0];
    const int* labels = (const int*)d_in[1];
    const float* mask = (const float*)d_in[2];

    const int BT = in_sizes[1];
    const int T = 4096;
    const int B = BT / T;
    const int chunks = T / TILE;
    const int nblocks = B * chunks;   // 2048

    build_desc_kernel<<<1, 256>>>(mask);
    ner_main_kernel<<<nblocks, TDIM>>>(logits, labels, (float*)d_out, T, nblocks);
}